// round 14
// baseline (speedup 1.0000x reference)
#include <cuda_runtime.h>

namespace {
constexpr int P    = 32;
constexpr int Cin  = 9;
constexpr int H    = 64;
constexpr int OUTC = 128;
constexpr int FS   = 36;   // fT row stride (floats); 16B-aligned rows
constexpr float EPS = 1e-5f;
}

// Main-loop weights live in the constant bank (separate cache port; frees
// l1tex wavefronts). 2304 + 32768 + 16384 = 51456 B < 64 KB.
__constant__ float cw_pre[Cin * H];
__constant__ float cw_m1[2 * H * H];   // full [128,64]: rows 0..63 main, 64..127 pctr
__constant__ float cw_m2[H * H];

using ull = unsigned long long;

struct SB {
  float  fT[2][H][FS];     // activations [q][channel][point]; pre-layer overlays ptsT here
  float  mk[2][P];
  float2 pooled2[H];       // {q0,q1} interleaved
  ull    part[2][H];       // split-k partials (pctr / o1)
  float2 pctr2[H];
  float2 feat2[H];
  float2 hid2[H];
  int    s_mode;
  int    s_valid[2];
};

__device__ __forceinline__ ull fma2(ull a, ull b, ull c) {
  ull d;
  asm("fma.rn.f32x2 %0, %1, %2, %3;" : "=l"(d) : "l"(a), "l"(b), "l"(c));
  return d;
}
__device__ __forceinline__ ull dup2(float x) {
  ull d; unsigned u = __float_as_uint(x);
  asm("mov.b64 %0, {%1, %1};" : "=l"(d) : "r"(u));
  return d;
}
__device__ __forceinline__ float2 unpk(ull v) {
  unsigned a, b;
  asm("mov.b64 {%0, %1}, %2;" : "=r"(a), "=r"(b) : "l"(v));
  return make_float2(__uint_as_float(a), __uint_as_float(b));
}
// BN fold, single channel, duplicated into both f32x2 lanes
__device__ __forceinline__ void bn1(const float* g, const float* be,
                                    const float* rm, const float* rv,
                                    const float* b, int h, ull& Ad, ull& Bd) {
  float s = __ldg(&g[h]) * rsqrtf(__ldg(&rv[h]) + EPS);
  float c = (__ldg(&b[h]) - __ldg(&rm[h])) * s + __ldg(&be[h]);
  Ad = dup2(s);
  Bd = dup2(c);
}

// 16 fma2: weights dup'd per channel, x arrives as packed point pairs
#define MMA_K(WV)                                                            \
  {                                                                          \
    ull wd0 = dup2((WV).x), wd1 = dup2((WV).y);                              \
    ull wd2 = dup2((WV).z), wd3 = dup2((WV).w);                              \
    ulonglong2 xa = *(const ulonglong2*)&sb->fT[0][k][p0];                   \
    ulonglong2 xb = *(const ulonglong2*)&sb->fT[1][k][p0];                   \
    acc[0][0][0]=fma2(xa.x,wd0,acc[0][0][0]); acc[0][0][1]=fma2(xa.y,wd0,acc[0][0][1]); \
    acc[0][1][0]=fma2(xa.x,wd1,acc[0][1][0]); acc[0][1][1]=fma2(xa.y,wd1,acc[0][1][1]); \
    acc[0][2][0]=fma2(xa.x,wd2,acc[0][2][0]); acc[0][2][1]=fma2(xa.y,wd2,acc[0][2][1]); \
    acc[0][3][0]=fma2(xa.x,wd3,acc[0][3][0]); acc[0][3][1]=fma2(xa.y,wd3,acc[0][3][1]); \
    acc[1][0][0]=fma2(xb.x,wd0,acc[1][0][0]); acc[1][0][1]=fma2(xb.y,wd0,acc[1][0][1]); \
    acc[1][1][0]=fma2(xb.x,wd1,acc[1][1][0]); acc[1][1][1]=fma2(xb.y,wd1,acc[1][1][1]); \
    acc[1][2][0]=fma2(xb.x,wd2,acc[1][2][0]); acc[1][2][1]=fma2(xb.y,wd2,acc[1][2][1]); \
    acc[1][3][0]=fma2(xb.x,wd3,acc[1][3][0]); acc[1][3][1]=fma2(xb.y,wd3,acc[1][3][1]); \
  }

__global__ void __launch_bounds__(128)
pnet_kernel(const float* __restrict__ poly,
            const void*  __restrict__ mask,
            const float* __restrict__ pre_b,
            const float* __restrict__ pre_g, const float* __restrict__ pre_be,
            const float* __restrict__ pre_rm, const float* __restrict__ pre_rv,
            const float* __restrict__ m1_b,
            const float* __restrict__ m1_g,  const float* __restrict__ m1_be,
            const float* __restrict__ m1_rm, const float* __restrict__ m1_rv,
            const float* __restrict__ m2_b,
            const float* __restrict__ m2_g,  const float* __restrict__ m2_be,
            const float* __restrict__ m2_rm, const float* __restrict__ m2_rv,
            const float* __restrict__ o1_w,  const float* __restrict__ o1_b,
            const float* __restrict__ o2_w,  const float* __restrict__ o2_b,
            float* __restrict__ out)
{
  __shared__ __align__(16) SB sbs;
  SB* sb = &sbs;

  const int blk = blockIdx.x;          // polylines 2*blk, 2*blk+1
  const int tid = threadIdx.x;         // 0..127
  const int cg  = tid >> 3;            // 0..15  -> 4 channels each
  const int pg  = tid & 7;             // 0..7   -> 4 points each
  const int h0  = cg * 4;
  const int p0  = pg * 4;

  // ---- mask dtype detection (int32 vs float32 vs byte) ----
  if (tid == 0) {
    const unsigned* w32 = (const unsigned*)mask;
    bool big = false, allf = true;
    #pragma unroll
    for (int i = 0; i < 32; i++) {
      unsigned v = w32[i];
      big  |= (v > 1u);
      allf &= (v == 0u || v == 0x3f800000u);
    }
    sb->s_mode = big ? (allf ? 1 : 2) : 0;
  }
  __syncthreads();
  const int mode = sb->s_mode;

  // ---- load points TRANSPOSED into fT overlay: ptsT[q][c][p] ----
  float* ptsT = (float*)sb->fT;        // 576 floats << fT region
  {
    const float* pp = poly + (long long)(2 * blk) * (P * Cin);
    for (int i = tid; i < 2 * P * Cin; i += 128) {
      int q = i / (P * Cin), r = i % (P * Cin);
      int p = r / Cin, c = r % Cin;
      ptsT[q * 288 + c * 32 + p] = pp[i];
    }
  }
  if (tid < 64) {
    int q = tid >> 5, t = tid & 31;
    int gi = (2 * blk + q) * P + t;
    float mv;
    if (mode == 2)      mv = ((const unsigned char*)mask)[gi] ? 1.f : 0.f;
    else if (mode == 1) mv = (((const float*)mask)[gi] != 0.f) ? 1.f : 0.f;
    else                mv = ((const int*)mask)[gi] ? 1.f : 0.f;
    sb->mk[q][t] = mv;
    unsigned bal = __ballot_sync(0xffffffffu, mv != 0.f);
    if (t == 0) sb->s_valid[q] = (bal != 0u) ? 1 : 0;
  }
  __syncthreads();

  ull acc[2][4][2];    // [q][channel][point-pair]
  ull Ad[4], Bd[4];

  // ================= pre layer: [P,9] @ [9,64] =============================
  #pragma unroll
  for (int q = 0; q < 2; q++)
    #pragma unroll
    for (int c = 0; c < 4; c++) { acc[q][c][0] = 0ull; acc[q][c][1] = 0ull; }

  #pragma unroll 3
  for (int k = 0; k < Cin; k++) {
    float4 wv = *(const float4*)&cw_pre[k * H + h0];
    ull wd0 = dup2(wv.x), wd1 = dup2(wv.y), wd2 = dup2(wv.z), wd3 = dup2(wv.w);
    ulonglong2 xa = *(const ulonglong2*)&ptsT[k * 32 + p0];
    ulonglong2 xb = *(const ulonglong2*)&ptsT[288 + k * 32 + p0];
    acc[0][0][0]=fma2(xa.x,wd0,acc[0][0][0]); acc[0][0][1]=fma2(xa.y,wd0,acc[0][0][1]);
    acc[0][1][0]=fma2(xa.x,wd1,acc[0][1][0]); acc[0][1][1]=fma2(xa.y,wd1,acc[0][1][1]);
    acc[0][2][0]=fma2(xa.x,wd2,acc[0][2][0]); acc[0][2][1]=fma2(xa.y,wd2,acc[0][2][1]);
    acc[0][3][0]=fma2(xa.x,wd3,acc[0][3][0]); acc[0][3][1]=fma2(xa.y,wd3,acc[0][3][1]);
    acc[1][0][0]=fma2(xb.x,wd0,acc[1][0][0]); acc[1][0][1]=fma2(xb.y,wd0,acc[1][0][1]);
    acc[1][1][0]=fma2(xb.x,wd1,acc[1][1][0]); acc[1][1][1]=fma2(xb.y,wd1,acc[1][1][1]);
    acc[1][2][0]=fma2(xb.x,wd2,acc[1][2][0]); acc[1][2][1]=fma2(xb.y,wd2,acc[1][2][1]);
    acc[1][3][0]=fma2(xb.x,wd3,acc[1][3][0]); acc[1][3][1]=fma2(xb.y,wd3,acc[1][3][1]);
  }
  #pragma unroll
  for (int c = 0; c < 4; c++) bn1(pre_g, pre_be, pre_rm, pre_rv, pre_b, h0 + c, Ad[c], Bd[c]);
  {
    float4 sv[2][4];
    #pragma unroll
    for (int q = 0; q < 2; q++) {
      float mv0 = sb->mk[q][p0],     mv1 = sb->mk[q][p0 + 1];
      float mv2 = sb->mk[q][p0 + 2], mv3 = sb->mk[q][p0 + 3];
      #pragma unroll
      for (int c = 0; c < 4; c++) {
        float2 rA = unpk(fma2(acc[q][c][0], Ad[c], Bd[c]));
        float2 rB = unpk(fma2(acc[q][c][1], Ad[c], Bd[c]));
        sv[q][c] = make_float4(fmaxf(rA.x, 0.f) * mv0, fmaxf(rA.y, 0.f) * mv1,
                               fmaxf(rB.x, 0.f) * mv2, fmaxf(rB.y, 0.f) * mv3);
      }
    }
    __syncthreads();   // all ptsT reads done before fT overwrite
    #pragma unroll
    for (int q = 0; q < 2; q++)
      #pragma unroll
      for (int c = 0; c < 4; c++)
        *(float4*)&sb->fT[q][h0 + c][p0] = sv[q][c];
  }
  __syncthreads();

  // ===== max-pool over points: thread = (q, channel) =======================
  {
    int q = tid >> 6, ch = tid & 63;
    const float4* row = (const float4*)&sb->fT[q][ch][0];
    float m = 0.f;
    #pragma unroll
    for (int g = 0; g < 8; g++) {
      float4 v = row[g];
      m = fmaxf(m, fmaxf(fmaxf(v.x, v.y), fmaxf(v.z, v.w)));
    }
    (&sb->pooled2[ch].x)[q] = m;
  }
  __syncthreads();

  const ull ONE = dup2(1.f);

  // pctr = pooled @ m1_w[64:128,:], split-k over 2 halves (constant weights)
  {
    int half = tid >> 6, ch = tid & 63;
    int kb = half * 32;
    ull a = 0ull;
    #pragma unroll 8
    for (int k = 0; k < 32; k++) {
      float wv = cw_m1[(H + kb + k) * H + ch];
      a = fma2(*(const ull*)&sb->pooled2[kb + k], dup2(wv), a);
    }
    sb->part[half][ch] = a;
  }
  __syncthreads();
  if (tid < 64) {
    ull s = fma2(sb->part[0][tid], ONE, sb->part[1][tid]);
    float2 r = unpk(s);
    sb->pctr2[tid] = r;
  }
  __syncthreads();

  // ================= m1: [P,64] @ m1_w[0:64,:] + pctr ======================
  #pragma unroll
  for (int c = 0; c < 4; c++) {
    float2 pc = sb->pctr2[h0 + c];
    acc[0][c][0] = acc[0][c][1] = dup2(pc.x);
    acc[1][c][0] = acc[1][c][1] = dup2(pc.y);
  }
  #pragma unroll 4
  for (int k = 0; k < H; k++) {
    float4 wv = *(const float4*)&cw_m1[k * H + h0];
    MMA_K(wv)
  }
  #pragma unroll
  for (int c = 0; c < 4; c++) bn1(m1_g, m1_be, m1_rm, m1_rv, m1_b, h0 + c, Ad[c], Bd[c]);
  {
    float4 sv[2][4];
    #pragma unroll
    for (int q = 0; q < 2; q++)
      #pragma unroll
      for (int c = 0; c < 4; c++) {
        float2 rA = unpk(fma2(acc[q][c][0], Ad[c], Bd[c]));
        float2 rB = unpk(fma2(acc[q][c][1], Ad[c], Bd[c]));
        sv[q][c] = make_float4(fmaxf(rA.x, 0.f), fmaxf(rA.y, 0.f),
                               fmaxf(rB.x, 0.f), fmaxf(rB.y, 0.f));
      }
    __syncthreads();   // all fT reads done
    #pragma unroll
    for (int q = 0; q < 2; q++)
      #pragma unroll
      for (int c = 0; c < 4; c++)
        *(float4*)&sb->fT[q][h0 + c][p0] = sv[q][c];
  }
  __syncthreads();

  // ================= m2: [P,64] @ [64,64], masked ==========================
  #pragma unroll
  for (int q = 0; q < 2; q++)
    #pragma unroll
    for (int c = 0; c < 4; c++) { acc[q][c][0] = 0ull; acc[q][c][1] = 0ull; }

  #pragma unroll 4
  for (int k = 0; k < H; k++) {
    float4 wv = *(const float4*)&cw_m2[k * H + h0];
    MMA_K(wv)
  }
  #pragma unroll
  for (int c = 0; c < 4; c++) bn1(m2_g, m2_be, m2_rm, m2_rv, m2_b, h0 + c, Ad[c], Bd[c]);
  {
    float4 sv[2][4];
    #pragma unroll
    for (int q = 0; q < 2; q++) {
      float mv0 = sb->mk[q][p0],     mv1 = sb->mk[q][p0 + 1];
      float mv2 = sb->mk[q][p0 + 2], mv3 = sb->mk[q][p0 + 3];
      #pragma unroll
      for (int c = 0; c < 4; c++) {
        float2 rA = unpk(fma2(acc[q][c][0], Ad[c], Bd[c]));
        float2 rB = unpk(fma2(acc[q][c][1], Ad[c], Bd[c]));
        sv[q][c] = make_float4(fmaxf(rA.x, 0.f) * mv0, fmaxf(rA.y, 0.f) * mv1,
                               fmaxf(rB.x, 0.f) * mv2, fmaxf(rB.y, 0.f) * mv3);
      }
    }
    __syncthreads();
    #pragma unroll
    for (int q = 0; q < 2; q++)
      #pragma unroll
      for (int c = 0; c < 4; c++)
        *(float4*)&sb->fT[q][h0 + c][p0] = sv[q][c];
  }
  __syncthreads();

  // ===== feat = max-pool over points =======================================
  {
    int q = tid >> 6, ch = tid & 63;
    const float4* row = (const float4*)&sb->fT[q][ch][0];
    float m = 0.f;
    #pragma unroll
    for (int g = 0; g < 8; g++) {
      float4 v = row[g];
      m = fmaxf(m, fmaxf(fmaxf(v.x, v.y), fmaxf(v.z, v.w)));
    }
    (&sb->feat2[ch].x)[q] = m;
  }
  __syncthreads();

  // ===== head layer 1: hid = relu(feat @ o1_w + o1_b), split-k =============
  {
    int half = tid >> 6, ch = tid & 63;
    int kb = half * 32;
    ull a = 0ull;
    #pragma unroll 8
    for (int k = 0; k < 32; k++) {
      float wv = __ldg(&o1_w[(kb + k) * H + ch]);
      a = fma2(*(const ull*)&sb->feat2[kb + k], dup2(wv), a);
    }
    sb->part[half][ch] = a;
  }
  __syncthreads();
  if (tid < 64) {
    ull s = fma2(sb->part[0][tid], ONE, sb->part[1][tid]);
    s = fma2(dup2(__ldg(&o1_b[tid])), ONE, s);
    float2 r = unpk(s);
    sb->hid2[tid] = make_float2(fmaxf(r.x, 0.f), fmaxf(r.y, 0.f));
  }
  __syncthreads();

  // ===== head layer 2: out = hid @ o2_w + o2_b, j = tid ====================
  {
    float vf0 = sb->s_valid[0] ? 1.f : 0.f;
    float vf1 = sb->s_valid[1] ? 1.f : 0.f;
    ull a = dup2(__ldg(&o2_b[tid]));
    #pragma unroll 8
    for (int k = 0; k < H; k++) {
      float wv = __ldg(&o2_w[k * OUTC + tid]);
      a = fma2(*(const ull*)&sb->hid2[k], dup2(wv), a);
    }
    float2 r = unpk(a);
    out[(long long)(2 * blk) * OUTC + tid]     = r.x * vf0;
    out[(long long)(2 * blk + 1) * OUTC + tid] = r.y * vf1;
  }
}

extern "C" void kernel_launch(void* const* d_in, const int* in_sizes, int n_in,
                              void* d_out, int out_size)
{
  (void)in_sizes; (void)n_in;
  const int n_poly = out_size / OUTC;   // B*N = 16384 (even)
  // Stage main-loop weights into the constant bank (D2D memcpy nodes;
  // graph-capturable, allocation-free, deterministic).
  cudaMemcpyToSymbolAsync(cw_pre, d_in[2],  Cin * H * sizeof(float),   0,
                          cudaMemcpyDeviceToDevice);
  cudaMemcpyToSymbolAsync(cw_m1,  d_in[8],  2 * H * H * sizeof(float), 0,
                          cudaMemcpyDeviceToDevice);
  cudaMemcpyToSymbolAsync(cw_m2,  d_in[14], H * H * sizeof(float),     0,
                          cudaMemcpyDeviceToDevice);
  pnet_kernel<<<n_poly / 2, 128>>>(
      (const float*)d_in[0],  d_in[1],
      (const float*)d_in[3],
      (const float*)d_in[4],  (const float*)d_in[5],
      (const float*)d_in[6],  (const float*)d_in[7],
      (const float*)d_in[9],
      (const float*)d_in[10], (const float*)d_in[11],
      (const float*)d_in[12], (const float*)d_in[13],
      (const float*)d_in[15],
      (const float*)d_in[16], (const float*)d_in[17],
      (const float*)d_in[18], (const float*)d_in[19],
      (const float*)d_in[20], (const float*)d_in[21],
      (const float*)d_in[22], (const float*)d_in[23],
      (float*)d_out);
}

// round 15
// speedup vs baseline: 5.0345x; 5.0345x over previous
#include <cuda_runtime.h>
#include <cstdint>

namespace {
constexpr int P = 32, Cin = 9, H = 64, OUTC = 128, Q = 4;
constexpr int XS = 68;   // X row stride (floats): conflict-free A-fragment loads
constexpr int WS = 72;   // W row stride (floats): conflict-free B-fragment loads
constexpr float EPS = 1e-5f;
// smem layout (float offsets)
constexpr int O_X    = 0;                 // X[128][XS]
constexpr int O_W    = 128 * XS;          // W[64][WS]
constexpr int O_SC   = O_W + 64 * WS;     // scales [3][64]
constexpr int O_SH   = O_SC + 192;        // shifts [3][64]
constexpr int O_MK   = O_SH + 192;        // mask  [4][32]
constexpr int O_PL   = O_MK + 128;        // pooled[4][64]
constexpr int O_PC   = O_PL + 256;        // pctr  [4][64]
constexpr int O_FT   = O_PC + 256;        // feat4 [64] float4 (interleaved q)
constexpr int O_HD   = O_FT + 256;        // hid4  [64] float4
constexpr int O_MISC = O_HD + 256;        // valid[4], mode
constexpr int SMEM_BYTES = (O_MISC + 8) * 4;   // 59424 B
}

using ull = unsigned long long;

__device__ __forceinline__ uint32_t tf32r(float x) {
  uint32_t u; asm("cvt.rna.tf32.f32 %0, %1;" : "=r"(u) : "f"(x)); return u;
}
__device__ __forceinline__ void mma8(float* c, const uint32_t* a, uint32_t b0, uint32_t b1) {
  asm volatile("mma.sync.aligned.m16n8k8.row.col.f32.tf32.tf32.f32 "
    "{%0,%1,%2,%3}, {%4,%5,%6,%7}, {%8,%9}, {%0,%1,%2,%3};"
    : "+f"(c[0]), "+f"(c[1]), "+f"(c[2]), "+f"(c[3])
    : "r"(a[0]), "r"(a[1]), "r"(a[2]), "r"(a[3]), "r"(b0), "r"(b1));
}
__device__ __forceinline__ ull fma2(ull a, ull b, ull c) {
  ull d; asm("fma.rn.f32x2 %0, %1, %2, %3;" : "=l"(d) : "l"(a), "l"(b), "l"(c));
  return d;
}
__device__ __forceinline__ ull dup2(float x) {
  ull d; unsigned u = __float_as_uint(x);
  asm("mov.b64 %0, {%1, %1};" : "=l"(d) : "r"(u)); return d;
}
__device__ __forceinline__ float2 unpk(ull v) {
  unsigned a, b; asm("mov.b64 {%0, %1}, %2;" : "=r"(a), "=r"(b) : "l"(v));
  return make_float2(__uint_as_float(a), __uint_as_float(b));
}

__global__ void __launch_bounds__(128)
pnet_tc(const float* __restrict__ poly, const void* __restrict__ mask,
        const float* __restrict__ pre_w, const float* __restrict__ pre_b,
        const float* __restrict__ pre_g, const float* __restrict__ pre_be,
        const float* __restrict__ pre_rm, const float* __restrict__ pre_rv,
        const float* __restrict__ m1_w, const float* __restrict__ m1_b,
        const float* __restrict__ m1_g, const float* __restrict__ m1_be,
        const float* __restrict__ m1_rm, const float* __restrict__ m1_rv,
        const float* __restrict__ m2_w, const float* __restrict__ m2_b,
        const float* __restrict__ m2_g, const float* __restrict__ m2_be,
        const float* __restrict__ m2_rm, const float* __restrict__ m2_rv,
        const float* __restrict__ o1_w, const float* __restrict__ o1_b,
        const float* __restrict__ o2_w, const float* __restrict__ o2_b,
        float* __restrict__ out, int n_poly)
{
  extern __shared__ __align__(16) float S[];
  float*  Xs     = S + O_X;
  float*  Wsm    = S + O_W;
  float*  sc     = S + O_SC;
  float*  sh     = S + O_SH;
  float*  mk     = S + O_MK;
  float*  pooled = S + O_PL;
  float*  pctr   = S + O_PC;
  float4* feat4  = (float4*)(S + O_FT);
  float4* hid4   = (float4*)(S + O_HD);
  int*    misc   = (int*)(S + O_MISC);

  const int tid = threadIdx.x, w = tid >> 5, lane = tid & 31;
  const int g = lane >> 2, t4 = lane & 3;
  const int pbase = blockIdx.x * Q;
  const bool okq = (pbase + w) < n_poly;

  // ---- mask dtype detection ----
  if (tid == 0) {
    const unsigned* w32 = (const unsigned*)mask;
    bool big = false, allf = true;
    #pragma unroll
    for (int i = 0; i < 32; i++) {
      unsigned v = w32[i];
      big |= (v > 1u); allf &= (v == 0u || v == 0x3f800000u);
    }
    misc[4] = big ? (allf ? 1 : 2) : 0;
  }
  // BN scales + shifts
  if (tid < 64) {
    int c = tid;
    float s0 = pre_g[c] * rsqrtf(pre_rv[c] + EPS);
    sc[c] = s0;       sh[c]       = (pre_b[c] - pre_rm[c]) * s0 + pre_be[c];
    float s1 = m1_g[c] * rsqrtf(m1_rv[c] + EPS);
    sc[64 + c] = s1;  sh[64 + c]  = (m1_b[c] - m1_rm[c]) * s1 + m1_be[c];
    float s2 = m2_g[c] * rsqrtf(m2_rv[c] + EPS);
    sc[128 + c] = s2; sh[128 + c] = (m2_b[c] - m2_rm[c]) * s2 + m2_be[c];
  }
  __syncthreads();
  const int mode = misc[4];

  // ---- mask (warp = polyline, lane = point) ----
  {
    long long gi = (long long)(pbase + w) * P + lane;
    float mv = 0.f;
    if (okq) {
      if (mode == 2)      mv = ((const unsigned char*)mask)[gi] ? 1.f : 0.f;
      else if (mode == 1) mv = (((const float*)mask)[gi] != 0.f) ? 1.f : 0.f;
      else                mv = ((const int*)mask)[gi] ? 1.f : 0.f;
    }
    mk[w * 32 + lane] = mv;
    unsigned bal = __ballot_sync(0xffffffffu, mv != 0.f);
    if (lane == 0) misc[w] = (bal != 0u) ? 1 : 0;
  }

  // ---- stage W_pre (16x64, zero-padded K, scale-folded, tf32) ----
  for (int i = tid; i < 16 * 64; i += 128) {
    int k = i >> 6, n = i & 63;
    float v = (k < Cin) ? __ldg(&pre_w[k * H + n]) * sc[n] : 0.f;
    ((uint32_t*)Wsm)[k * WS + n] = tf32r(v);
  }
  // ---- stage X_pre: thread t = row (point), cols 0..15 ----
  {
    int q = tid >> 5, p = tid & 31;
    const float* prow = poly + ((long long)(pbase + q) * P + p) * Cin;
    bool ok = (pbase + q) < n_poly;
    uint32_t* xr = (uint32_t*)Xs + tid * XS;
    #pragma unroll
    for (int c = 0; c < 16; c++) {
      float x = (ok && c < Cin) ? __ldg(&prow[c]) : 0.f;
      xr[c] = tf32r(x);
    }
  }
  __syncthreads();

  float acc[2][8][4];

  // ================= GEMM1: X[128x16] @ Wpre[16x64] =================
  #pragma unroll
  for (int mt = 0; mt < 2; mt++)
    #pragma unroll
    for (int nt = 0; nt < 8; nt++)
      #pragma unroll
      for (int j = 0; j < 4; j++) acc[mt][nt][j] = 0.f;

  #pragma unroll
  for (int kt = 0; kt < 2; kt++) {
    uint32_t A[2][4];
    #pragma unroll
    for (int mt = 0; mt < 2; mt++) {
      const uint32_t* xb = (const uint32_t*)Xs + (32 * w + 16 * mt) * XS + 8 * kt;
      A[mt][0] = xb[g * XS + t4];        A[mt][1] = xb[(g + 8) * XS + t4];
      A[mt][2] = xb[g * XS + t4 + 4];    A[mt][3] = xb[(g + 8) * XS + t4 + 4];
    }
    #pragma unroll
    for (int nt = 0; nt < 8; nt++) {
      const uint32_t* wb = (const uint32_t*)Wsm + (8 * kt) * WS + 8 * nt;
      uint32_t b0 = wb[t4 * WS + g], b1 = wb[(t4 + 4) * WS + g];
      mma8(acc[0][nt], A[0], b0, b1);
      mma8(acc[1][nt], A[1], b0, b1);
    }
  }
  __syncthreads();   // all X/W reads done

  // epilogue1: relu(c+sh)*mask -> X (tf32); stage W_m1 lower
  #pragma unroll
  for (int mt = 0; mt < 2; mt++) {
    int r0 = 32 * w + 16 * mt + g;
    float mv0 = mk[w * 32 + 16 * mt + g], mv1 = mk[w * 32 + 16 * mt + g + 8];
    #pragma unroll
    for (int nt = 0; nt < 8; nt++) {
      int n0 = 8 * nt + 2 * t4;
      float s00 = sh[n0], s01 = sh[n0 + 1];
      uint32_t* xr0 = (uint32_t*)Xs + r0 * XS + n0;
      uint32_t* xr1 = (uint32_t*)Xs + (r0 + 8) * XS + n0;
      xr0[0] = tf32r(fmaxf(acc[mt][nt][0] + s00, 0.f) * mv0);
      xr0[1] = tf32r(fmaxf(acc[mt][nt][1] + s01, 0.f) * mv0);
      xr1[0] = tf32r(fmaxf(acc[mt][nt][2] + s00, 0.f) * mv1);
      xr1[1] = tf32r(fmaxf(acc[mt][nt][3] + s01, 0.f) * mv1);
    }
  }
  for (int i = tid; i < 64 * 64; i += 128) {
    int k = i >> 6, n = i & 63;
    ((uint32_t*)Wsm)[k * WS + n] = tf32r(__ldg(&m1_w[k * H + n]) * sc[64 + n]);
  }
  __syncthreads();

  // ===== pooled[w][ch] = max over this polyline's points =====
  #pragma unroll
  for (int half = 0; half < 2; half++) {
    int ch = lane + 32 * half;
    float m = 0.f;
    #pragma unroll 8
    for (int p = 0; p < 32; p++) m = fmaxf(m, Xs[(32 * w + p) * XS + ch]);
    pooled[w * 64 + ch] = m;
  }
  __syncthreads();

  // ===== pctr = (pooled @ m1_w_upper) * scale_m1 (fp32) =====
  {
    int pair = tid >> 6, ch = tid & 63;
    float a0 = 0.f, a1 = 0.f;
    #pragma unroll 8
    for (int k = 0; k < 64; k++) {
      float wv = __ldg(&m1_w[(H + k) * H + ch]);
      a0 = fmaf(pooled[(2 * pair) * 64 + k], wv, a0);
      a1 = fmaf(pooled[(2 * pair + 1) * 64 + k], wv, a1);
    }
    float s = sc[64 + ch];
    pctr[(2 * pair) * 64 + ch]     = a0 * s;
    pctr[(2 * pair + 1) * 64 + ch] = a1 * s;
  }
  __syncthreads();

  // ================= GEMM2: X[128x64] @ Wm1[64x64] =================
  #pragma unroll
  for (int mt = 0; mt < 2; mt++)
    #pragma unroll
    for (int nt = 0; nt < 8; nt++)
      #pragma unroll
      for (int j = 0; j < 4; j++) acc[mt][nt][j] = 0.f;

  #pragma unroll 4
  for (int kt = 0; kt < 8; kt++) {
    uint32_t A[2][4];
    #pragma unroll
    for (int mt = 0; mt < 2; mt++) {
      const uint32_t* xb = (const uint32_t*)Xs + (32 * w + 16 * mt) * XS + 8 * kt;
      A[mt][0] = xb[g * XS + t4];        A[mt][1] = xb[(g + 8) * XS + t4];
      A[mt][2] = xb[g * XS + t4 + 4];    A[mt][3] = xb[(g + 8) * XS + t4 + 4];
    }
    #pragma unroll
    for (int nt = 0; nt < 8; nt++) {
      const uint32_t* wb = (const uint32_t*)Wsm + (8 * kt) * WS + 8 * nt;
      uint32_t b0 = wb[t4 * WS + g], b1 = wb[(t4 + 4) * WS + g];
      mma8(acc[0][nt], A[0], b0, b1);
      mma8(acc[1][nt], A[1], b0, b1);
    }
  }
  __syncthreads();

  // epilogue2: relu(c+pctr+sh_m1) -> X (tf32); stage W_m2
  #pragma unroll
  for (int mt = 0; mt < 2; mt++) {
    int r0 = 32 * w + 16 * mt + g;
    #pragma unroll
    for (int nt = 0; nt < 8; nt++) {
      int n0 = 8 * nt + 2 * t4;
      float c00 = pctr[w * 64 + n0] + sh[64 + n0];
      float c01 = pctr[w * 64 + n0 + 1] + sh[64 + n0 + 1];
      uint32_t* xr0 = (uint32_t*)Xs + r0 * XS + n0;
      uint32_t* xr1 = (uint32_t*)Xs + (r0 + 8) * XS + n0;
      xr0[0] = tf32r(fmaxf(acc[mt][nt][0] + c00, 0.f));
      xr0[1] = tf32r(fmaxf(acc[mt][nt][1] + c01, 0.f));
      xr1[0] = tf32r(fmaxf(acc[mt][nt][2] + c00, 0.f));
      xr1[1] = tf32r(fmaxf(acc[mt][nt][3] + c01, 0.f));
    }
  }
  for (int i = tid; i < 64 * 64; i += 128) {
    int k = i >> 6, n = i & 63;
    ((uint32_t*)Wsm)[k * WS + n] = tf32r(__ldg(&m2_w[k * H + n]) * sc[128 + n]);
  }
  __syncthreads();

  // ================= GEMM3: X[128x64] @ Wm2[64x64] =================
  #pragma unroll
  for (int mt = 0; mt < 2; mt++)
    #pragma unroll
    for (int nt = 0; nt < 8; nt++)
      #pragma unroll
      for (int j = 0; j < 4; j++) acc[mt][nt][j] = 0.f;

  #pragma unroll 4
  for (int kt = 0; kt < 8; kt++) {
    uint32_t A[2][4];
    #pragma unroll
    for (int mt = 0; mt < 2; mt++) {
      const uint32_t* xb = (const uint32_t*)Xs + (32 * w + 16 * mt) * XS + 8 * kt;
      A[mt][0] = xb[g * XS + t4];        A[mt][1] = xb[(g + 8) * XS + t4];
      A[mt][2] = xb[g * XS + t4 + 4];    A[mt][3] = xb[(g + 8) * XS + t4 + 4];
    }
    #pragma unroll
    for (int nt = 0; nt < 8; nt++) {
      const uint32_t* wb = (const uint32_t*)Wsm + (8 * kt) * WS + 8 * nt;
      uint32_t b0 = wb[t4 * WS + g], b1 = wb[(t4 + 4) * WS + g];
      mma8(acc[0][nt], A[0], b0, b1);
      mma8(acc[1][nt], A[1], b0, b1);
    }
  }
  __syncthreads();

  // epilogue3: relu(c+sh_m2)*mask -> X (fp32, feeds pooling only)
  #pragma unroll
  for (int mt = 0; mt < 2; mt++) {
    int r0 = 32 * w + 16 * mt + g;
    float mv0 = mk[w * 32 + 16 * mt + g], mv1 = mk[w * 32 + 16 * mt + g + 8];
    #pragma unroll
    for (int nt = 0; nt < 8; nt++) {
      int n0 = 8 * nt + 2 * t4;
      float s00 = sh[128 + n0], s01 = sh[128 + n0 + 1];
      float* xr0 = Xs + r0 * XS + n0;
      float* xr1 = Xs + (r0 + 8) * XS + n0;
      xr0[0] = fmaxf(acc[mt][nt][0] + s00, 0.f) * mv0;
      xr0[1] = fmaxf(acc[mt][nt][1] + s01, 0.f) * mv0;
      xr1[0] = fmaxf(acc[mt][nt][2] + s00, 0.f) * mv1;
      xr1[1] = fmaxf(acc[mt][nt][3] + s01, 0.f) * mv1;
    }
  }
  __syncthreads();

  // ===== feat pooling -> feat4[ch] interleaved {q0,q1,q2,q3} =====
  #pragma unroll
  for (int half = 0; half < 2; half++) {
    int ch = lane + 32 * half;
    float m = 0.f;
    #pragma unroll 8
    for (int p = 0; p < 32; p++) m = fmaxf(m, Xs[(32 * w + p) * XS + ch]);
    ((float*)&feat4[ch])[w] = m;
  }
  __syncthreads();

  // ===== head o1: hid = relu(feat @ o1_w + o1_b) =====
  {
    int pair = tid >> 6, ch = tid & 63;
    ull a = 0ull;
    #pragma unroll 8
    for (int k = 0; k < 64; k++) {
      float wv = __ldg(&o1_w[k * H + ch]);
      a = fma2(*(const ull*)((const float*)&feat4[k] + 2 * pair), dup2(wv), a);
    }
    float bia = __ldg(&o1_b[ch]);
    float2 r = unpk(a);
    ((float*)&hid4[ch])[2 * pair]     = fmaxf(r.x + bia, 0.f);
    ((float*)&hid4[ch])[2 * pair + 1] = fmaxf(r.y + bia, 0.f);
  }
  __syncthreads();

  // ===== head o2: out = hid @ o2_w + o2_b =====
  {
    float vf0 = misc[0] ? 1.f : 0.f, vf1 = misc[1] ? 1.f : 0.f;
    float vf2 = misc[2] ? 1.f : 0.f, vf3 = misc[3] ? 1.f : 0.f;
    ull a01 = dup2(__ldg(&o2_b[tid])), a23 = a01;
    #pragma unroll 8
    for (int k = 0; k < 64; k++) {
      float wv = __ldg(&o2_w[k * OUTC + tid]);
      ull wd = dup2(wv);
      const ull* hp = (const ull*)&hid4[k];
      a01 = fma2(hp[0], wd, a01);
      a23 = fma2(hp[1], wd, a23);
    }
    float2 r01 = unpk(a01), r23 = unpk(a23);
    long long ob = (long long)pbase * OUTC + tid;
    if (pbase + 0 < n_poly) out[ob]            = r01.x * vf0;
    if (pbase + 1 < n_poly) out[ob + OUTC]     = r01.y * vf1;
    if (pbase + 2 < n_poly) out[ob + 2 * OUTC] = r23.x * vf2;
    if (pbase + 3 < n_poly) out[ob + 3 * OUTC] = r23.y * vf3;
  }
}

extern "C" void kernel_launch(void* const* d_in, const int* in_sizes, int n_in,
                              void* d_out, int out_size)
{
  (void)in_sizes; (void)n_in;
  const int n_poly = out_size / OUTC;   // 16384
  const int nblk = (n_poly + Q - 1) / Q;
  cudaFuncSetAttribute(pnet_tc, cudaFuncAttributeMaxDynamicSharedMemorySize, SMEM_BYTES);
  pnet_tc<<<nblk, 128, SMEM_BYTES>>>(
      (const float*)d_in[0],  d_in[1],
      (const float*)d_in[2],  (const float*)d_in[3],
      (const float*)d_in[4],  (const float*)d_in[5],
      (const float*)d_in[6],  (const float*)d_in[7],
      (const float*)d_in[8],  (const float*)d_in[9],
      (const float*)d_in[10], (const float*)d_in[11],
      (const float*)d_in[12], (const float*)d_in[13],
      (const float*)d_in[14], (const float*)d_in[15],
      (const float*)d_in[16], (const float*)d_in[17],
      (const float*)d_in[18], (const float*)d_in[19],
      (const float*)d_in[20], (const float*)d_in[21],
      (const float*)d_in[22], (const float*)d_in[23],
      (float*)d_out, n_poly);
}